// round 13
// baseline (speedup 1.0000x reference)
#include <cuda_runtime.h>

#define HH 256
#define WW 256
#define MAXSLICES 64
#define TPC 16              // CTAs (16-col tiles) per slice
#define CSTRIDE 17          // u16 row stride for g tile (odd shift: conflict-free)
#define PAD 8               // guard rows of BIG on each side of the g tile
#define GROWS (HH + 2 * PAD)
#define LUTCAP 2312         // floats fitting in the gs region (9248 B)

// ---- device globals (allocation-free scratch / rendezvous state) ----
__device__ unsigned g_bits[MAXSLICES * (HH * WW / 32)];   // 2048 words/slice
__device__ int g_ticket[MAXSLICES];                       // monotonic, reset-free
__device__ int g_pmax[MAXSLICES][TPC];                    // overwritten each replay

// ================= K_pre: pack mask bits (bandwidth-bound, ~2.8us) ========
__global__ void __launch_bounds__(256) k_pack(const float* __restrict__ in)
{
    const int base = blockIdx.x * 2048 + threadIdx.x;
    #pragma unroll
    for (int i = 0; i < 8; i++) {
        int n = base + i * 256;
        bool m = (in[n] != 0.0f);
        unsigned b = __ballot_sync(0xffffffffu, m);
        if ((threadIdx.x & 31) == 0) g_bits[n >> 5] = b;
    }
}

__device__ __forceinline__ void spin_until(volatile int* p, int target)
{
    while (*p < target) __nanosleep(32);
}

// ================= fused: g -> exact min-plus -> rendezvous -> LUT write ===
// CTA = (slice, 16-col tile); 256 threads = 16 cols x 16 row-groups of 16 rows.
__global__ void __launch_bounds__(256, 6)
wdt_fused(float* __restrict__ out)
{
    __shared__ unsigned       bm[HH * 8];             // 8192 B: bitmask; reused as d2 park
    __shared__ unsigned short gs[GROWS * CSTRIDE];    // 9248 B: padded g tile; reused as LUT
    __shared__ int   s_red;
    __shared__ int   s_m2;
    __shared__ float s_rinv;

    const int slice = blockIdx.x >> 4;
    const int ct    = blockIdx.x & 15;
    const int t     = threadIdx.x;
    float* oslab = out + (size_t)slice * (HH * WW) + ct * 16;
    unsigned short* gsp = gs + PAD * CSTRIDE;         // row 0 of the real tile

    if (t == 0) s_red = 0;

    // ---- phase 1: load packed slice bitmask + fill guard rows ----
    {
        const uint4* src4 = reinterpret_cast<const uint4*>(g_bits + slice * 2048);
        uint4* bm4 = reinterpret_cast<uint4*>(bm);
        bm4[t]       = src4[t];
        bm4[t + 256] = src4[t + 256];
        // guard rows: g = BIG -> candidate 512^2 + dd^2 can never win
        if (t < PAD * CSTRIDE) {
            gs[t]                         = 512;
            gs[(PAD + HH) * CSTRIDE + t]  = 512;
        }
    }
    __syncthreads();

    // ---- phase 2: horizontal nearest-zero distance via funnel-shift windows ----
    const int col  = t & 15;
    const int gcol = ct * 16 + col;
    const int j    = gcol & 31;
    const int wi   = gcol >> 5;               // CTA-uniform word index
    const int q0   = (t >> 4) * 16;           // this thread's 16 rows

    for (int r = q0; r < q0 + 16; r++) {
        const unsigned* row = bm + r * 8;     // broadcast LDS reads (uniform wi)
        unsigned cur = row[wi];
        int gv = 0;
        if ((cur >> j) & 1) {
            unsigned prevw = (wi > 0) ? row[wi - 1] : 0xffffffffu;  // outside: no zeros
            unsigned nextw = (wi < 7) ? row[wi + 1] : 0xffffffffu;

            int dl, dr;
            unsigned yl = ~__funnelshift_rc(prevw, cur, j + 1);
            if (yl) dl = __clz(yl);
            else {                              // zero farther than 31 left (rare)
                dl = 512;                       // BIG = H + W (matches reference clamp)
                for (int d = 32; d <= gcol && dl == 512; d++) {
                    int cc = gcol - d;
                    if (!((row[cc >> 5] >> (cc & 31)) & 1)) dl = d;
                }
            }
            unsigned yr = ~__funnelshift_rc(cur, nextw, j + 1);
            if (yr) dr = __ffs(yr);
            else {                              // zero farther than 32 right (rare)
                dr = 512;
                for (int d = 33; gcol + d < WW && dr == 512; d++) {
                    int cc = gcol + d;
                    if (!((row[cc >> 5] >> (cc & 31)) & 1)) dr = d;
                }
            }
            gv = min(dl, dr);
        }
        gsp[r * CSTRIDE + col] = (unsigned short)gv;
    }
    __syncthreads();          // phase 2 done; bm is dead -> becomes the d2 park

    // ---- phase 3: exact vertical min-plus, fixed dd=1..4 window + residual ----
    // Fixed part: 8 INDEPENDENT padded LDS per row (no bounds branches, no
    // loop-carried chain) -> MLP hides latency. Residual loop from dd=5 only
    // when best > 25 (rare); exactness: all dd with dd^2 < final best evaluated.
    int colmax = 0;
    unsigned pair = 0;
    #pragma unroll
    for (int k = 0; k < 16; k++) {
        int q = q0 + k;
        const unsigned short* gcol_p = gsp + q * CSTRIDE + col;
        int gv = gcol_p[0];
        int best = gv * gv;
        {
            int a1 = gcol_p[-1 * CSTRIDE], b1 = gcol_p[ 1 * CSTRIDE];
            int a2 = gcol_p[-2 * CSTRIDE], b2 = gcol_p[ 2 * CSTRIDE];
            int a3 = gcol_p[-3 * CSTRIDE], b3 = gcol_p[ 3 * CSTRIDE];
            int a4 = gcol_p[-4 * CSTRIDE], b4 = gcol_p[ 4 * CSTRIDE];
            best = min(best, a1 * a1 + 1);  best = min(best, b1 * b1 + 1);
            best = min(best, a2 * a2 + 4);  best = min(best, b2 * b2 + 4);
            best = min(best, a3 * a3 + 9);  best = min(best, b3 * b3 + 9);
            best = min(best, a4 * a4 + 16); best = min(best, b4 * b4 + 16);
        }
        if (best > 25) {
            for (int dd = 5; dd * dd < best; dd++) {
                int ddsq = dd * dd;
                int u = q - dd, v = q + dd;
                if (u >= 0) { int c = gsp[u * CSTRIDE + col]; c = c * c + ddsq; if (c < best) best = c; }
                if (v < HH) { int c = gsp[v * CSTRIDE + col]; c = c * c + ddsq; if (c < best) best = c; }
            }
        }
        if (best > colmax) colmax = best;
        unsigned pb = (unsigned)min(best, 65535);   // exact whenever the slice has any zero
        if ((k & 1) == 0) pair = pb;
        else              bm[(k >> 1) * 256 + t] = pair | (pb << 16);
    }

    // ---- phase 4: CTA max, then TPC-way reset-free rendezvous ----
    #pragma unroll
    for (int off = 16; off; off >>= 1)
        colmax = max(colmax, __shfl_xor_sync(0xffffffffu, colmax, off));
    if ((t & 31) == 0) atomicMax(&s_red, colmax);
    __syncthreads();          // also: all phase-3 gs reads done -> gs reusable

    if (t == 0) {
        g_pmax[slice][ct] = s_red;                  // plain store each replay
        __threadfence();
        int tk = atomicAdd(&g_ticket[slice], 1);    // monotonic ticket
        int target = (tk & ~(TPC - 1)) + TPC;       // my replay's group of TPC
        spin_until(&g_ticket[slice], target);
        __threadfence();
        int m2 = 0;
        #pragma unroll
        for (int i = 0; i < TPC; i++) m2 = max(m2, __ldcg(&g_pmax[slice][i]));
        s_m2 = m2;
        s_rinv = (m2 > 0) ? rsqrtf((float)m2) : 0.0f;
    }
    __syncthreads();

    const int   m2   = s_m2;
    const float rinv = s_rinv;
    float* lut = reinterpret_cast<float*>(gs);      // gs is dead -> LUT region

    // ---- phase 5a: build sqrt-LUT (~m2 MUFU per CTA instead of 4096) ----
    if (m2 > 0 && m2 < LUTCAP) {
        for (int i = t; i <= m2; i += 256)
            lut[i] = 1.0f - sqrtf((float)i) * rinv;
    }
    __syncthreads();

    // ---- phase 5b: normalized output, written exactly once (coalesced) ----
    if (m2 > 0 && m2 < LUTCAP) {
        #pragma unroll
        for (int i = 0; i < 8; i++) {
            unsigned w = bm[i * 256 + t];           // park: d2 <= m2 -> LUT-safe
            int q = q0 + 2 * i;
            oslab[q * WW + col]       = lut[w & 0xffffu];
            oslab[(q + 1) * WW + col] = lut[w >> 16];
        }
    } else if (m2 > 0) {
        // pathological huge distances: exact per-pixel sqrt fallback
        #pragma unroll
        for (int i = 0; i < 8; i++) {
            unsigned w = bm[i * 256 + t];
            int q = q0 + 2 * i;
            oslab[q * WW + col]       = 1.0f - sqrtf((float)(w & 0xffffu)) * rinv;
            oslab[(q + 1) * WW + col] = 1.0f - sqrtf((float)(w >> 16)) * rinv;
        }
    } else {
        // whole slice background: dt == 0 everywhere, reference outputs dt (= 0)
        #pragma unroll
        for (int i = 0; i < 16; i++) oslab[(q0 + i) * WW + col] = 0.0f;
    }
}

extern "C" void kernel_launch(void* const* d_in, const int* in_sizes, int n_in,
                              void* d_out, int out_size)
{
    const float* in = (const float*)d_in[0];
    float* out = (float*)d_out;

    int slices = in_sizes[0] / (HH * WW);   // 48 for the reference shapes
    if (slices > MAXSLICES) slices = MAXSLICES;

    // Pin max smem carveout: 6 CTAs/SM (6 x 17.6KB = 105.4KB) never smem-limited.
    cudaFuncSetAttribute(wdt_fused, cudaFuncAttributePreferredSharedMemoryCarveout, 100);

    k_pack<<<slices * 32, 256>>>(in);
    // launch_bounds(256,6): capacity 148*6 = 888 >= grid 768 -> all CTAs
    // co-resident -> the max rendezvous cannot deadlock.
    wdt_fused<<<slices * TPC, 256>>>(out);
}

// round 14
// speedup vs baseline: 1.4510x; 1.4510x over previous
#include <cuda_runtime.h>

#define HH 256
#define WW 256
#define MAXSLICES 64
#define TPC 16              // CTAs (16-col tiles) per slice
#define CSTRIDE 18          // u16 row stride (9 words, even -> u32-aligned pair reads)
#define LUTCAP 2304         // floats fitting in the gs region (9216 B)

// ---- device globals (allocation-free scratch / rendezvous state) ----
__device__ unsigned g_bits[MAXSLICES * (HH * WW / 32)];   // 2048 words/slice
__device__ int g_ticket[MAXSLICES];                       // monotonic, reset-free
__device__ int g_pmax[MAXSLICES][TPC];                    // overwritten each replay

// ================= K_pre: pack mask bits (bandwidth-bound, ~2.8us) ========
__global__ void __launch_bounds__(256) k_pack(const float* __restrict__ in)
{
    const int base = blockIdx.x * 2048 + threadIdx.x;
    #pragma unroll
    for (int i = 0; i < 8; i++) {
        int n = base + i * 256;
        bool m = (in[n] != 0.0f);
        unsigned b = __ballot_sync(0xffffffffu, m);
        if ((threadIdx.x & 31) == 0) g_bits[n >> 5] = b;
    }
}

__device__ __forceinline__ void spin_until(volatile int* p, int target)
{
    while (*p < target) __nanosleep(32);
}

// ================= fused: g -> exact min-plus -> rendezvous -> LUT write ===
// CTA = (slice, 16-col tile).
// Phase 2 mapping: 16 cols x 16 row-groups of 16 rows.
// Phase 3 mapping: 8 col-PAIRS x 32 row-groups of 8 rows (u32 = g pair).
__global__ void __launch_bounds__(256, 6)
wdt_fused(float* __restrict__ out)
{
    __shared__ unsigned       bm[HH * 8];           // 8192 B: bitmask; reused as d2 park
    __shared__ unsigned short gs[HH * CSTRIDE];     // 9216 B: g tile; reused as sqrt-LUT
    __shared__ int   s_red;
    __shared__ int   s_m2;
    __shared__ float s_rinv;

    const int slice = blockIdx.x >> 4;
    const int ct    = blockIdx.x & 15;
    const int t     = threadIdx.x;
    float* oslab = out + (size_t)slice * (HH * WW) + ct * 16;

    if (t == 0) s_red = 0;

    // ---- phase 1: load packed slice bitmask (vectorized, L2-resident) ----
    {
        const uint4* src4 = reinterpret_cast<const uint4*>(g_bits + slice * 2048);
        uint4* bm4 = reinterpret_cast<uint4*>(bm);
        bm4[t]       = src4[t];
        bm4[t + 256] = src4[t + 256];
    }
    __syncthreads();

    // ---- phase 2: horizontal nearest-zero distance via funnel-shift windows ----
    {
        const int col  = t & 15;
        const int gcol = ct * 16 + col;
        const int j    = gcol & 31;
        const int wi   = gcol >> 5;           // CTA-uniform word index
        const int r0   = (t >> 4) * 16;

        for (int r = r0; r < r0 + 16; r++) {
            const unsigned* row = bm + r * 8; // broadcast LDS reads (uniform wi)
            unsigned cur = row[wi];
            int gv = 0;
            if ((cur >> j) & 1) {
                unsigned prevw = (wi > 0) ? row[wi - 1] : 0xffffffffu;  // outside: no zeros
                unsigned nextw = (wi < 7) ? row[wi + 1] : 0xffffffffu;

                int dl, dr;
                unsigned yl = ~__funnelshift_rc(prevw, cur, j + 1);
                if (yl) dl = __clz(yl);
                else {                          // zero farther than 31 left (rare)
                    dl = 512;                   // BIG = H + W (matches reference clamp)
                    for (int d = 32; d <= gcol && dl == 512; d++) {
                        int cc = gcol - d;
                        if (!((row[cc >> 5] >> (cc & 31)) & 1)) dl = d;
                    }
                }
                unsigned yr = ~__funnelshift_rc(cur, nextw, j + 1);
                if (yr) dr = __ffs(yr);
                else {                          // zero farther than 32 right (rare)
                    dr = 512;
                    for (int d = 33; gcol + d < WW && dr == 512; d++) {
                        int cc = gcol + d;
                        if (!((row[cc >> 5] >> (cc & 31)) & 1)) dr = d;
                    }
                }
                gv = min(dl, dr);
            }
            gs[r * CSTRIDE + col] = (unsigned short)gv;
        }
    }
    __syncthreads();          // phase 2 done; bm is dead -> becomes the d2 park

    // ---- phase 3: exact vertical min-plus, 2 columns per thread via u32 ----
    // One LDS yields g for BOTH columns; adaptive shrinking-radius loop runs to
    // max(best0,best1) -> exact for each column.
    const int cp = t & 7;                     // column pair: cols 2cp, 2cp+1
    const int rg = t >> 3;                    // row group: rows rg*8 .. rg*8+7
    const int q0 = rg * 8;
    const unsigned* gsw = reinterpret_cast<const unsigned*>(gs);   // 9 words/row

    int colmax = 0;
    #pragma unroll
    for (int k = 0; k < 8; k++) {
        int q = q0 + k;
        unsigned w0 = gsw[q * 9 + cp];
        int ga = w0 & 0xffffu, gb = w0 >> 16;
        int best0 = ga * ga, best1 = gb * gb;
        int bmax = max(best0, best1);
        for (int dd = 1; dd * dd < bmax; dd++) {
            int ddsq = dd * dd;
            int u = q - dd, v = q + dd;
            if (u >= 0) {
                unsigned wu = gsw[u * 9 + cp];
                int a = wu & 0xffffu, b = wu >> 16;
                best0 = min(best0, a * a + ddsq);
                best1 = min(best1, b * b + ddsq);
            }
            if (v < HH) {
                unsigned wv = gsw[v * 9 + cp];
                int a = wv & 0xffffu, b = wv >> 16;
                best0 = min(best0, a * a + ddsq);
                best1 = min(best1, b * b + ddsq);
            }
            bmax = max(best0, best1);
        }
        colmax = max(colmax, bmax);
        // park both columns' d2 in one word (d2 <= 65535 whenever slice has a zero)
        bm[k * 256 + t] = (unsigned)min(best0, 65535) | ((unsigned)min(best1, 65535) << 16);
    }

    // ---- phase 4: CTA max, then TPC-way reset-free rendezvous ----
    #pragma unroll
    for (int off = 16; off; off >>= 1)
        colmax = max(colmax, __shfl_xor_sync(0xffffffffu, colmax, off));
    if ((t & 31) == 0) atomicMax(&s_red, colmax);
    __syncthreads();          // all phase-3 gs reads done -> gs reusable

    if (t == 0) {
        g_pmax[slice][ct] = s_red;                  // plain store each replay
        __threadfence();
        int tk = atomicAdd(&g_ticket[slice], 1);    // monotonic ticket
        int target = (tk & ~(TPC - 1)) + TPC;       // my replay's group of TPC
        spin_until(&g_ticket[slice], target);
        __threadfence();
        int m2 = 0;
        #pragma unroll
        for (int i = 0; i < TPC; i++) m2 = max(m2, __ldcg(&g_pmax[slice][i]));
        s_m2 = m2;
        s_rinv = (m2 > 0) ? rsqrtf((float)m2) : 0.0f;
    }
    __syncthreads();

    const int   m2   = s_m2;
    const float rinv = s_rinv;
    float* lut = reinterpret_cast<float*>(gs);      // gs is dead -> LUT region

    // ---- phase 5a: build sqrt-LUT (~m2 MUFU per CTA instead of 4096) ----
    if (m2 > 0 && m2 < LUTCAP) {
        for (int i = t; i <= m2; i += 256)
            lut[i] = 1.0f - sqrtf((float)i) * rinv;
    }
    __syncthreads();

    // ---- phase 5b: output via float2 (adjacent cols), written exactly once ----
    float2* opair = reinterpret_cast<float2*>(oslab + 2 * cp);   // 8B-aligned
    if (m2 > 0 && m2 < LUTCAP) {
        #pragma unroll
        for (int k = 0; k < 8; k++) {
            unsigned w = bm[k * 256 + t];
            float2 v = make_float2(lut[w & 0xffffu], lut[w >> 16]);
            opair[(q0 + k) * (WW / 2)] = v;
        }
    } else if (m2 > 0) {
        // pathological huge distances: exact per-pixel sqrt fallback
        #pragma unroll
        for (int k = 0; k < 8; k++) {
            unsigned w = bm[k * 256 + t];
            float2 v = make_float2(1.0f - sqrtf((float)(w & 0xffffu)) * rinv,
                                   1.0f - sqrtf((float)(w >> 16)) * rinv);
            opair[(q0 + k) * (WW / 2)] = v;
        }
    } else {
        // whole slice background: dt == 0 everywhere, reference outputs dt (= 0)
        #pragma unroll
        for (int k = 0; k < 8; k++)
            opair[(q0 + k) * (WW / 2)] = make_float2(0.0f, 0.0f);
    }
}

extern "C" void kernel_launch(void* const* d_in, const int* in_sizes, int n_in,
                              void* d_out, int out_size)
{
    const float* in = (const float*)d_in[0];
    float* out = (float*)d_out;

    int slices = in_sizes[0] / (HH * WW);   // 48 for the reference shapes
    if (slices > MAXSLICES) slices = MAXSLICES;

    // Pin max smem carveout: 6 CTAs/SM (6 x 17.3KB = 104KB) never smem-limited.
    cudaFuncSetAttribute(wdt_fused, cudaFuncAttributePreferredSharedMemoryCarveout, 100);

    k_pack<<<slices * 32, 256>>>(in);
    // launch_bounds(256,6): capacity 148*6 = 888 >= grid 768 -> all CTAs
    // co-resident -> the max rendezvous cannot deadlock.
    wdt_fused<<<slices * TPC, 256>>>(out);
}

// round 15
// speedup vs baseline: 1.6250x; 1.1199x over previous
#include <cuda_runtime.h>

#define HH 256
#define WW 256
#define MAXSLICES 64
#define TPC 16              // CTAs (16-col tiles) per slice
#define CSTRIDE 18          // u16 row stride (9 words, even -> u32 pair access)
#define LUTCAP 2304         // floats fitting in the gs region (9216 B)

// ---- device globals (allocation-free scratch / rendezvous state) ----
__device__ unsigned g_bits[MAXSLICES * (HH * WW / 32)];   // 2048 words/slice
__device__ int g_ticket[MAXSLICES];                       // monotonic, reset-free
__device__ int g_pmax[MAXSLICES][TPC];                    // overwritten each replay

// ================= K_pre: pack mask bits (bandwidth-bound, ~2.8us) ========
__global__ void __launch_bounds__(256) k_pack(const float* __restrict__ in)
{
    const int base = blockIdx.x * 2048 + threadIdx.x;
    #pragma unroll
    for (int i = 0; i < 8; i++) {
        int n = base + i * 256;
        bool m = (in[n] != 0.0f);
        unsigned b = __ballot_sync(0xffffffffu, m);
        if ((threadIdx.x & 31) == 0) g_bits[n >> 5] = b;
    }
}

__device__ __forceinline__ void spin_until(volatile int* p, int target)
{
    while (*p < target) __nanosleep(32);
}

// ================= fused: g -> exact min-plus -> rendezvous -> LUT write ===
// CTA = (slice, 16-col tile). Uniform mapping for phases 2/3/5:
//   cp = t&7  -> column pair (2cp, 2cp+1);  rg = t>>3 -> rows rg*8..rg*8+7.
__global__ void __launch_bounds__(256, 6)
wdt_fused(float* __restrict__ out)
{
    __shared__ unsigned       bm[HH * 8];           // 8192 B: slice bitmask
    __shared__ unsigned short gs[HH * CSTRIDE];     // 9216 B: g tile; reused as sqrt-LUT
    __shared__ int   s_red;
    __shared__ int   s_m2;
    __shared__ float s_rinv;

    const int slice = blockIdx.x >> 4;
    const int ct    = blockIdx.x & 15;
    const int t     = threadIdx.x;
    float* oslab = out + (size_t)slice * (HH * WW) + ct * 16;

    if (t == 0) s_red = 0;

    // ---- phase 1: load packed slice bitmask (vectorized, L2-resident) ----
    {
        const uint4* src4 = reinterpret_cast<const uint4*>(g_bits + slice * 2048);
        uint4* bm4 = reinterpret_cast<uint4*>(bm);
        bm4[t]       = src4[t];
        bm4[t + 256] = src4[t + 256];
    }
    __syncthreads();

    const int cp = t & 7;                     // column pair within tile
    const int rg = t >> 3;                    // row group
    const int q0 = rg * 8;
    unsigned* gsw = reinterpret_cast<unsigned*>(gs);   // 9 words/row

    // ---- phase 2: horizontal nearest-zero distance, paired + branch-free ----
    // Funnel windows: yl bit31 = pixel's own bit -> clz(yl)=0 for background
    // pixels automatically (no divergent branch). Shift clamps handle j=31.
    {
        const int j0    = (ct & 1) * 16 + 2 * cp;     // both cols in same word
        const int wi    = ct >> 1;                    // CTA-uniform word index
        const int gcol0 = ct * 16 + 2 * cp;

        for (int r = q0; r < q0 + 8; r++) {
            const unsigned* row = bm + r * 8;         // broadcast LDS (uniform wi)
            unsigned cur   = row[wi];
            unsigned prevw = (wi > 0) ? row[wi - 1] : 0xffffffffu;  // outside: no zeros
            unsigned nextw = (wi < 7) ? row[wi + 1] : 0xffffffffu;

            int g0, g1;
            {   // column j0
                unsigned yl = ~__funnelshift_rc(prevw, cur, j0 + 1);
                unsigned yr = ~__funnelshift_rc(cur, nextw, j0 + 1);
                int dl, dr;
                if (yl) dl = __clz(yl);
                else {                                // >=32 ones left (p ~ 2^-31)
                    dl = 512;                         // BIG = H + W (reference clamp)
                    for (int d = 32; d <= gcol0 && dl == 512; d++) {
                        int cc = gcol0 - d;
                        if (!((row[cc >> 5] >> (cc & 31)) & 1)) dl = d;
                    }
                }
                if (yr) dr = __ffs(yr);
                else {
                    dr = 512;
                    for (int d = 33; gcol0 + d < WW && dr == 512; d++) {
                        int cc = gcol0 + d;
                        if (!((row[cc >> 5] >> (cc & 31)) & 1)) dr = d;
                    }
                }
                g0 = min(dl, dr);
            }
            {   // column j0+1
                unsigned yl = ~__funnelshift_rc(prevw, cur, j0 + 2);
                unsigned yr = ~__funnelshift_rc(cur, nextw, j0 + 2);
                int dl, dr;
                if (yl) dl = __clz(yl);
                else {
                    dl = 512;
                    for (int d = 32; d <= gcol0 + 1 && dl == 512; d++) {
                        int cc = gcol0 + 1 - d;
                        if (!((row[cc >> 5] >> (cc & 31)) & 1)) dl = d;
                    }
                }
                if (yr) dr = __ffs(yr);
                else {
                    dr = 512;
                    for (int d = 33; gcol0 + 1 + d < WW && dr == 512; d++) {
                        int cc = gcol0 + 1 + d;
                        if (!((row[cc >> 5] >> (cc & 31)) & 1)) dr = d;
                    }
                }
                g1 = min(dl, dr);
            }
            gsw[r * 9 + cp] = (unsigned)g0 | ((unsigned)g1 << 16);  // one STS.32
        }
    }
    __syncthreads();

    // ---- phase 3: exact vertical min-plus, 2 cols/thread, results in regs ----
    // d2[q] = min_r' g[r']^2 + (q-r')^2; adaptive radius to max(best0,best1): exact.
    unsigned pk[8];
    int colmax = 0;
    #pragma unroll
    for (int k = 0; k < 8; k++) {
        int q = q0 + k;
        unsigned w0 = gsw[q * 9 + cp];
        int ga = w0 & 0xffffu, gb = w0 >> 16;
        int best0 = ga * ga, best1 = gb * gb;
        int bmax = max(best0, best1);
        for (int dd = 1; dd * dd < bmax; dd++) {
            int ddsq = dd * dd;
            int u = q - dd, v = q + dd;
            if (u >= 0) {
                unsigned wu = gsw[u * 9 + cp];
                int a = wu & 0xffffu, b = wu >> 16;
                best0 = min(best0, a * a + ddsq);
                best1 = min(best1, b * b + ddsq);
            }
            if (v < HH) {
                unsigned wv = gsw[v * 9 + cp];
                int a = wv & 0xffffu, b = wv >> 16;
                best0 = min(best0, a * a + ddsq);
                best1 = min(best1, b * b + ddsq);
            }
            bmax = max(best0, best1);
        }
        colmax = max(colmax, bmax);
        pk[k] = (unsigned)min(best0, 65535) | ((unsigned)min(best1, 65535) << 16);
    }

    // ---- phase 4: CTA max, then TPC-way reset-free rendezvous ----
    #pragma unroll
    for (int off = 16; off; off >>= 1)
        colmax = max(colmax, __shfl_xor_sync(0xffffffffu, colmax, off));
    if ((t & 31) == 0) atomicMax(&s_red, colmax);
    __syncthreads();          // all phase-3 gs reads done -> gs reusable

    if (t == 0) {
        g_pmax[slice][ct] = s_red;                  // plain store each replay
        __threadfence();
        int tk = atomicAdd(&g_ticket[slice], 1);    // monotonic ticket
        int target = (tk & ~(TPC - 1)) + TPC;       // my replay's group of TPC
        spin_until(&g_ticket[slice], target);
        __threadfence();
        int m2 = 0;
        #pragma unroll
        for (int i = 0; i < TPC; i++) m2 = max(m2, __ldcg(&g_pmax[slice][i]));
        s_m2 = m2;
        s_rinv = (m2 > 0) ? rsqrtf((float)m2) : 0.0f;
    }
    __syncthreads();

    const int   m2   = s_m2;
    const float rinv = s_rinv;
    float* lut = reinterpret_cast<float*>(gs);      // gs is dead -> LUT region

    // ---- phase 5a: build sqrt-LUT (~m2 MUFU per CTA instead of 4096) ----
    if (m2 > 0 && m2 < LUTCAP) {
        for (int i = t; i <= m2; i += 256)
            lut[i] = 1.0f - sqrtf((float)i) * rinv;
    }
    __syncthreads();

    // ---- phase 5b: output from regs via float2, written exactly once ----
    float2* opair = reinterpret_cast<float2*>(oslab + 2 * cp);   // 8B-aligned
    if (m2 > 0 && m2 < LUTCAP) {
        #pragma unroll
        for (int k = 0; k < 8; k++) {
            unsigned w = pk[k];
            opair[(q0 + k) * (WW / 2)] = make_float2(lut[w & 0xffffu], lut[w >> 16]);
        }
    } else if (m2 > 0) {
        // pathological huge distances: exact per-pixel sqrt fallback
        #pragma unroll
        for (int k = 0; k < 8; k++) {
            unsigned w = pk[k];
            opair[(q0 + k) * (WW / 2)] =
                make_float2(1.0f - sqrtf((float)(w & 0xffffu)) * rinv,
                            1.0f - sqrtf((float)(w >> 16)) * rinv);
        }
    } else {
        // whole slice background: dt == 0 everywhere, reference outputs dt (= 0)
        #pragma unroll
        for (int k = 0; k < 8; k++)
            opair[(q0 + k) * (WW / 2)] = make_float2(0.0f, 0.0f);
    }
}

extern "C" void kernel_launch(void* const* d_in, const int* in_sizes, int n_in,
                              void* d_out, int out_size)
{
    const float* in = (const float*)d_in[0];
    float* out = (float*)d_out;

    int slices = in_sizes[0] / (HH * WW);   // 48 for the reference shapes
    if (slices > MAXSLICES) slices = MAXSLICES;

    // Pin max smem carveout: 6 CTAs/SM (6 x 17.3KB = 104KB) never smem-limited.
    cudaFuncSetAttribute(wdt_fused, cudaFuncAttributePreferredSharedMemoryCarveout, 100);

    k_pack<<<slices * 32, 256>>>(in);
    // launch_bounds(256,6): capacity 148*6 = 888 >= grid 768 -> all CTAs
    // co-resident -> the max rendezvous cannot deadlock.
    wdt_fused<<<slices * TPC, 256>>>(out);
}